// round 16
// baseline (speedup 1.0000x reference)
#include <cuda_runtime.h>
#include <cstdint>

#define TPB 128

// ---------------- precomputed tables (device globals; no allocation) --------
__device__ float g_Vtab[216 * 32];
__device__ float g_Etab[216 * 216];     // exp(score)
__device__ float g_Ttab[20439 * 27];    // outputs for all prefixes with t<=2

// ---------------- packed f32x2 helpers ----------------
__device__ __forceinline__ unsigned long long fma2(unsigned long long a,
                                                   unsigned long long b,
                                                   unsigned long long c) {
    unsigned long long d;
    asm("fma.rn.f32x2 %0, %1, %2, %3;" : "=l"(d) : "l"(a), "l"(b), "l"(c));
    return d;
}
__device__ __forceinline__ unsigned long long pack2(float lo, float hi) {
    unsigned long long r;
    asm("mov.b64 %0, {%1, %2};" : "=l"(r) : "f"(lo), "f"(hi));
    return r;
}
__device__ __forceinline__ void unpack2(float& lo, float& hi, unsigned long long v) {
    asm("mov.b64 {%0, %1}, %2;" : "=f"(lo), "=f"(hi) : "l"(v));
}

// ------- merged pre-kernel: E (exp scores) + V table, block per k-row -------
// score(q,k) = x_q . (Wq . K_k)  -- no Q/K tables needed.
__global__ void ek_kernel(const float* __restrict__ tokE,
                          const float* __restrict__ posE,
                          const float* __restrict__ Wq,
                          const float* __restrict__ Wk,
                          const float* __restrict__ Wv) {
    __shared__ float xk[32], kk[32], uu[32];
    const int rk  = blockIdx.x;          // 0..215
    const int tok = rk >> 3, s = rk & 7;
    const int tid = threadIdx.x;
    if (tid < 32) xk[tid] = tokE[tok * 32 + tid] + posE[s * 32 + tid];
    __syncthreads();
    if (tid < 32) {
        float k = 0.f, v = 0.f;
#pragma unroll
        for (int d = 0; d < 32; d++) {
            k += xk[d] * Wk[d * 32 + tid];
            v += xk[d] * Wv[d * 32 + tid];
        }
        kk[tid] = k;
        g_Vtab[rk * 32 + tid] = v;
    }
    __syncthreads();
    if (tid < 32) {
        float u = 0.f;
#pragma unroll
        for (int n = 0; n < 32; n++) u += Wq[tid * 32 + n] * kk[n];
        uu[tid] = u;
    }
    __syncthreads();
    for (int rq = tid; rq < 216; rq += TPB) {
        int tq = rq & 7, tkq = rq >> 3;
        float acc = 0.f;
#pragma unroll
        for (int d = 0; d < 32; d++)
            acc += (tokE[tkq * 32 + d] + posE[tq * 32 + d]) * uu[d];
        g_Etab[rq * 216 + rk] = __expf(acc);   // scores O(1e-4): safe w/o max
    }
}

// ---------------- warp-level layernorm (lane = dim) ----------------
__device__ __forceinline__ float ln_warp(float v) {
    float s1 = v, s2 = v * v;
#pragma unroll
    for (int off = 16; off; off >>= 1) {
        s1 += __shfl_xor_sync(0xffffffffu, s1, off);
        s2 += __shfl_xor_sync(0xffffffffu, s2, off);
    }
    float mu  = s1 * (1.0f / 32.0f);
    float var = s2 * (1.0f / 32.0f) - mu * mu;
    return (v - mu) * rsqrtf(var + 1e-5f);
}

// ---------------- pre-kernel: prefix table, WARP per entry ----------------
__global__ void ttab_kernel(const float* __restrict__ tokE,
                            const float* __restrict__ posE,
                            const float* __restrict__ W1,
                            const float* __restrict__ W2,
                            const float* __restrict__ Wout) {
    const int wid  = (blockIdx.x * blockDim.x + threadIdx.x) >> 5;
    const int lane = threadIdx.x & 31;
    if (wid >= 20439) return;
    const int i = wid;
    int t, tk0 = 0, tk1 = 0, tk2 = 0;
    if (i < 27)       { t = 0; tk0 = i; }
    else if (i < 756) { t = 1; int j = i - 27; tk0 = j / 27; tk1 = j - tk0 * 27; }
    else              { t = 2; int j = i - 756; tk0 = j / 729;
                        tk1 = (j - tk0 * 729) / 27; tk2 = j - tk0 * 729 - tk1 * 27; }
    const int tokt = (t == 0) ? tk0 : ((t == 1) ? tk1 : tk2);
    const int d = lane;

    const float* E = g_Etab + (tokt * 8 + t) * 216;
    float w0 = E[tk0 * 8 + 0];
    float w1 = (t >= 1) ? E[tk1 * 8 + 1] : 0.0f;
    float w2 = (t >= 2) ? E[tk2 * 8 + 2] : 0.0f;
    const float inv = 1.0f / (w0 + w1 + w2);

    float n1 = tokE[tokt * 32 + d] + posE[t * 32 + d];
    n1 += (w0 * inv) * g_Vtab[(tk0 * 8 + 0) * 32 + d];
    if (t >= 1) n1 += (w1 * inv) * g_Vtab[(tk1 * 8 + 1) * 32 + d];
    if (t >= 2) n1 += (w2 * inv) * g_Vtab[(tk2 * 8 + 2) * 32 + d];
    n1 = ln_warp(n1);

    float h0 = 0.f, h1 = 0.f;
#pragma unroll
    for (int dd = 0; dd < 32; dd++) {
        float nd = __shfl_sync(0xffffffffu, n1, dd);
        h0 += nd * W1[dd * 64 + lane];
        h1 += nd * W1[dd * 64 + lane + 32];
    }
    h0 = fmaxf(h0, 0.f);
    h1 = fmaxf(h1, 0.f);
    float y = 0.f;
#pragma unroll
    for (int n = 0; n < 32; n++) {
        float a = __shfl_sync(0xffffffffu, h0, n);
        float b = __shfl_sync(0xffffffffu, h1, n);
        y += a * W2[n * 32 + d];
        y += b * W2[(n + 32) * 32 + d];
    }
    float n2 = ln_warp(y + n1);

    float acc = 0.f;
#pragma unroll
    for (int dd = 0; dd < 32; dd++) {
        float nd = __shfl_sync(0xffffffffu, n2, dd);
        acc += nd * ((lane < 27) ? Wout[dd * 27 + lane] : 0.0f);
    }
    if (lane < 27) g_Ttab[i * 27 + lane] = acc;
}

// ---------------- main kernel smem layout (floats) ----------------
static constexpr int OFF_W1   = 0;      // 32 x 64
static constexpr int OFF_W2   = 2048;   // 64 x 32
static constexpr int OFF_WOUT = 4096;   // 32 x 32 (cols 27..31 zero)
static constexpr int OFF_TOKE = 5120;   // 27 x 36
static constexpr int OFF_POSE = 6092;   // 8 x 36
static constexpr int OFF_VT   = 6380;   // 216 x 36  (V table; reused for out)
static constexpr int SMEM_FLOATS = 14156;
static constexpr int SMEM_BYTES  = SMEM_FLOATS * 4;   // 56624 B -> 4 CTAs/SM

extern __shared__ float sm[];

__device__ __forceinline__ void layernorm32(float* v) {
    float s1 = 0.0f, s2 = 0.0f;
#pragma unroll
    for (int e = 0; e < 32; e++) { s1 += v[e]; s2 += v[e] * v[e]; }
    float mu  = s1 * (1.0f / 32.0f);
    float var = s2 * (1.0f / 32.0f) - mu * mu;
    float rs  = rsqrtf(var + 1e-5f);
#pragma unroll
    for (int e = 0; e < 32; e++) v[e] = (v[e] - mu) * rs;
}

#define BPW 8   // batches per warp in the light path

__global__ void __launch_bounds__(TPB, 4)
mt_kernel(const int* __restrict__ tokens,
          const float* __restrict__ g_tokE, const float* __restrict__ g_posE,
          const float* __restrict__ g_W1,  const float* __restrict__ g_W2,
          const float* __restrict__ g_Wout,
          float* __restrict__ g_out,
          int na_blocks)
{
    const int tid = threadIdx.x;

    // ============ LIGHT PATH: t<=2 rows, warp-per-batch table copy =========
    if ((int)blockIdx.x >= na_blocks) {
        const int lane = tid & 31;
        const int gw = ((int)blockIdx.x - na_blocks) * 4 + (tid >> 5);
        const int bbase = gw * BPW;
        int4 tt[BPW];
#pragma unroll
        for (int b = 0; b < BPW; b++)
            tt[b] = *(const int4*)(tokens + (bbase + b) * 8);
#pragma unroll
        for (int b = 0; b < BPW; b++) {
            const int batch = bbase + b;
            const int idx0 = tt[b].x;
            const int idx1 = 27 + tt[b].x * 27 + tt[b].y;
            const int idx2 = 756 + tt[b].x * 729 + tt[b].y * 27 + tt[b].z;
            float* ob = g_out + (size_t)batch * 216;
#pragma unroll
            for (int k = 0; k < 3; k++) {
                int r = lane + 32 * k;
                if (r < 81) {
                    int t = (r >= 54) ? 2 : ((r >= 27) ? 1 : 0);
                    int c = r - t * 27;
                    int idx = (t == 0) ? idx0 : ((t == 1) ? idx1 : idx2);
                    ob[r] = __ldg(g_Ttab + idx * 27 + c);
                }
            }
        }
        return;
    }

    // ================= HEAVY PATH: t in 3..7 ================================
    float* s_W1   = sm + OFF_W1;
    float* s_W2   = sm + OFF_W2;
    float* s_Wout = sm + OFF_WOUT;
    float* s_tokE = sm + OFF_TOKE;
    float* s_posE = sm + OFF_POSE;
    float* s_VT   = sm + OFF_VT;

    // row mapping: hrow = batch*5 + (t-3)
    const int hrow0 = (int)blockIdx.x * 256 + tid;
    const int hrow1 = hrow0 + TPB;
    const int batch0 = hrow0 / 5;
    const int batch1 = hrow1 / 5;
    const int t0 = hrow0 - batch0 * 5 + 3;   // 3..7
    const int t1 = hrow1 - batch1 * 5 + 3;

    // ---- EARLY: token + score gathers (hide under staging stores) ----
    const int4 ta0 = *(const int4*)(tokens + batch0 * 8);
    const int4 tb0 = *(const int4*)(tokens + batch0 * 8 + 4);
    const int4 ta1 = *(const int4*)(tokens + batch1 * 8);
    const int4 tb1 = *(const int4*)(tokens + batch1 * 8 + 4);
    const int tk0[8] = {ta0.x, ta0.y, ta0.z, ta0.w, tb0.x, tb0.y, tb0.z, tb0.w};
    const int tk1[8] = {ta1.x, ta1.y, ta1.z, ta1.w, tb1.x, tb1.y, tb1.z, tb1.w};
    const int tok0 = tk0[t0 & 7] & 31;
    const int tok1 = tk1[t1 & 7] & 31;

    const int sb0 = (tok0 * 8 + t0) * 216;
    const int sb1 = (tok1 * 8 + t1) * 216;
    float p0[8], p1[8];
#pragma unroll
    for (int s = 0; s < 8; s++) {
        p0[s] = __ldg(g_Etab + sb0 + tk0[s] * 8 + s);
        p1[s] = __ldg(g_Etab + sb1 + tk1[s] * 8 + s);
    }

    // ---- cooperative staging ----
#pragma unroll
    for (int b = 0; b < 2048; b += TPB * 4) {
        int i = b + tid * 4;
        *(float4*)(s_W1 + i) = *(const float4*)(g_W1 + i);
        *(float4*)(s_W2 + i) = *(const float4*)(g_W2 + i);
    }
    for (int i = tid; i < 1024; i += TPB) {
        int e = i >> 5, c = i & 31;
        s_Wout[i] = (c < 27) ? g_Wout[e * 27 + c] : 0.0f;
    }
    for (int i = tid; i < 27 * 32; i += TPB) {
        int r = i >> 5, c = i & 31;
        s_tokE[r * 36 + c] = g_tokE[i];
    }
    for (int i = tid; i < 8 * 32; i += TPB) {
        int r = i >> 5, c = i & 31;
        s_posE[r * 36 + c] = g_posE[i];
    }
    for (int i = tid; i < 216 * 8; i += TPB) {
        int r = i >> 3, c = i & 7;
        *(float4*)(s_VT + r * 36 + c * 4) = *(const float4*)(g_Vtab + r * 32 + c * 4);
    }
    __syncthreads();

    // ---- softmax weights (causal; exp already applied) ----
    float sum0 = 0.0f, sum1 = 0.0f;
#pragma unroll
    for (int s = 0; s < 8; s++) {
        p0[s] = (s <= t0) ? p0[s] : 0.0f;
        p1[s] = (s <= t1) ? p1[s] : 0.0f;
        sum0 += p0[s]; sum1 += p1[s];
    }
    const float inv0 = 1.0f / sum0;
    const float inv1 = 1.0f / sum1;

    // ---- out = attn @ V ----
    unsigned long long o0[16], o1[16];
#pragma unroll
    for (int i = 0; i < 16; i++) { o0[i] = 0ULL; o1[i] = 0ULL; }
#pragma unroll
    for (int s = 0; s < 8; s++) {
        float a = p0[s] * inv0;
        float b = p1[s] * inv1;
        unsigned long long aa = pack2(a, a);
        unsigned long long bb = pack2(b, b);
        const ulonglong2* va = (const ulonglong2*)(s_VT + (tk0[s] * 8 + s) * 36);
        const ulonglong2* vb = (const ulonglong2*)(s_VT + (tk1[s] * 8 + s) * 36);
#pragma unroll
        for (int i = 0; i < 8; i++) {
            ulonglong2 wa = va[i], wb = vb[i];
            o0[2 * i]     = fma2(aa, wa.x, o0[2 * i]);
            o0[2 * i + 1] = fma2(aa, wa.y, o0[2 * i + 1]);
            o1[2 * i]     = fma2(bb, wb.x, o1[2 * i]);
            o1[2 * i + 1] = fma2(bb, wb.y, o1[2 * i + 1]);
        }
    }

    // ---- LN1(out + x); keep n1 PACKED (f32x2) to cut register pressure ----
    unsigned long long n1p0[16], n1p1[16];
    {
        float n1a[32], n1b[32];
#pragma unroll
        for (int i = 0; i < 8; i++) {
            float4 pa = *(const float4*)(s_posE + t0 * 36 + i * 4);
            float4 pb = *(const float4*)(s_posE + t1 * 36 + i * 4);
            float4 xa = *(const float4*)(s_tokE + tok0 * 36 + i * 4);
            float4 xb = *(const float4*)(s_tokE + tok1 * 36 + i * 4);
            float lo, hi;
            unpack2(lo, hi, o0[2 * i]);
            n1a[4 * i + 0] = lo + xa.x + pa.x;
            n1a[4 * i + 1] = hi + xa.y + pa.y;
            unpack2(lo, hi, o0[2 * i + 1]);
            n1a[4 * i + 2] = lo + xa.z + pa.z;
            n1a[4 * i + 3] = hi + xa.w + pa.w;
            unpack2(lo, hi, o1[2 * i]);
            n1b[4 * i + 0] = lo + xb.x + pb.x;
            n1b[4 * i + 1] = hi + xb.y + pb.y;
            unpack2(lo, hi, o1[2 * i + 1]);
            n1b[4 * i + 2] = lo + xb.z + pb.z;
            n1b[4 * i + 3] = hi + xb.w + pb.w;
        }
        layernorm32(n1a);
        layernorm32(n1b);
#pragma unroll
        for (int i = 0; i < 16; i++) {
            n1p0[i] = pack2(n1a[2 * i], n1a[2 * i + 1]);
            n1p1[i] = pack2(n1b[2 * i], n1b[2 * i + 1]);
        }
    }

    // ---- MLP: relu(n1 @ W1) @ W2, h in 16 chunks of 4 ----
    unsigned long long y0[16], y1[16];
#pragma unroll
    for (int i = 0; i < 16; i++) { y0[i] = 0ULL; y1[i] = 0ULL; }
#pragma unroll 1
    for (int c = 0; c < 16; c++) {
        unsigned long long h0[2], h1[2];
        h0[0] = h0[1] = h1[0] = h1[1] = 0ULL;
#pragma unroll
        for (int ep = 0; ep < 16; ep++) {
            float a0, a1, b0f, b1f;
            unpack2(a0, a1, n1p0[ep]);
            unpack2(b0f, b1f, n1p1[ep]);
            {
                unsigned long long ba = pack2(a0, a0);
                unsigned long long bb = pack2(b0f, b0f);
                ulonglong2 ww = *(const ulonglong2*)(s_W1 + (2 * ep) * 64 + c * 4);
                h0[0] = fma2(ba, ww.x, h0[0]);
                h0[1] = fma2(ba, ww.y, h0[1]);
                h1[0] = fma2(bb, ww.x, h1[0]);
                h1[1] = fma2(bb, ww.y, h1[1]);
            }
            {
                unsigned long long ba = pack2(a1, a1);
                unsigned long long bb = pack2(b1f, b1f);
                ulonglong2 ww = *(const ulonglong2*)(s_W1 + (2 * ep + 1) * 64 + c * 4);
                h0[0] = fma2(ba, ww.x, h0[0]);
                h0[1] = fma2(ba, ww.y, h0[1]);
                h1[0] = fma2(bb, ww.x, h1[0]);
                h1[1] = fma2(bb, ww.y, h1[1]);
            }
        }
#pragma unroll
        for (int j = 0; j < 2; j++) {
            float ha0, ha1, hb0, hb1;
            unpack2(ha0, ha1, h0[j]);
            unpack2(hb0, hb1, h1[j]);
            ha0 = fmaxf(ha0, 0.0f); ha1 = fmaxf(ha1, 0.0f);
            hb0 = fmaxf(hb0, 0.0f); hb1 = fmaxf(hb1, 0.0f);
            const ulonglong2* wa =
                (const ulonglong2*)(s_W2 + (c * 4 + 2 * j) * 32);
            {
                unsigned long long pa = pack2(ha0, ha0);
                unsigned long long pb = pack2(hb0, hb0);
#pragma unroll
                for (int i = 0; i < 8; i++) {
                    ulonglong2 ww = wa[i];
                    y0[2 * i]     = fma2(pa, ww.x, y0[2 * i]);
                    y0[2 * i + 1] = fma2(pa, ww.y, y0[2 * i + 1]);
                    y1[2 * i]     = fma2(pb, ww.x, y1[2 * i]);
                    y1[2 * i + 1] = fma2(pb, ww.y, y1[2 * i + 1]);
                }
            }
            {
                unsigned long long pa = pack2(ha1, ha1);
                unsigned long long pb = pack2(hb1, hb1);
                const ulonglong2* wb = wa + 8;
#pragma unroll
                for (int i = 0; i < 8; i++) {
                    ulonglong2 ww = wb[i];
                    y0[2 * i]     = fma2(pa, ww.x, y0[2 * i]);
                    y0[2 * i + 1] = fma2(pa, ww.y, y0[2 * i + 1]);
                    y1[2 * i]     = fma2(pb, ww.x, y1[2 * i]);
                    y1[2 * i + 1] = fma2(pb, ww.y, y1[2 * i + 1]);
                }
            }
        }
    }

    // ---- LN2(y + n1); pack n2 ----
    unsigned long long n2p0[16], n2p1[16];
    {
        float n2a[32], n2b[32];
#pragma unroll
        for (int i = 0; i < 16; i++) {
            float lo, hi, a, b;
            unpack2(lo, hi, y0[i]);
            unpack2(a, b, n1p0[i]);
            n2a[2 * i] = lo + a;  n2a[2 * i + 1] = hi + b;
            unpack2(lo, hi, y1[i]);
            unpack2(a, b, n1p1[i]);
            n2b[2 * i] = lo + a;  n2b[2 * i + 1] = hi + b;
        }
        layernorm32(n2a);
        layernorm32(n2b);
#pragma unroll
        for (int i = 0; i < 16; i++) {
            n2p0[i] = pack2(n2a[2 * i], n2a[2 * i + 1]);
            n2p1[i] = pack2(n2b[2 * i], n2b[2 * i + 1]);
        }
    }

    // ---- logits in two 16-col halves, staged straight to smem ----
    __syncthreads();   // all warps done with VT / tokE / posE regions
    float* s_out = s_VT;   // 256*27 = 6912 floats <= 7776
    float* oa = s_out + tid * 27;
    float* ob = s_out + (TPB + tid) * 27;
#pragma unroll
    for (int hh = 0; hh < 2; hh++) {
        unsigned long long l0[8], l1[8];
#pragma unroll
        for (int i = 0; i < 8; i++) { l0[i] = 0ULL; l1[i] = 0ULL; }
#pragma unroll
        for (int ep = 0; ep < 16; ep++) {
            float a0, a1, b0f, b1f;
            unpack2(a0, a1, n2p0[ep]);
            unpack2(b0f, b1f, n2p1[ep]);
            {
                unsigned long long ba = pack2(a0, a0);
                unsigned long long bb = pack2(b0f, b0f);
                const ulonglong2* w =
                    (const ulonglong2*)(s_Wout + (2 * ep) * 32 + hh * 16);
#pragma unroll
                for (int i = 0; i < 4; i++) {
                    ulonglong2 ww = w[i];
                    l0[2 * i]     = fma2(ba, ww.x, l0[2 * i]);
                    l0[2 * i + 1] = fma2(ba, ww.y, l0[2 * i + 1]);
                    l1[2 * i]     = fma2(bb, ww.x, l1[2 * i]);
                    l1[2 * i + 1] = fma2(bb, ww.y, l1[2 * i + 1]);
                }
            }
            {
                unsigned long long ba = pack2(a1, a1);
                unsigned long long bb = pack2(b1f, b1f);
                const ulonglong2* w =
                    (const ulonglong2*)(s_Wout + (2 * ep + 1) * 32 + hh * 16);
#pragma unroll
                for (int i = 0; i < 4; i++) {
                    ulonglong2 ww = w[i];
                    l0[2 * i]     = fma2(ba, ww.x, l0[2 * i]);
                    l0[2 * i + 1] = fma2(ba, ww.y, l0[2 * i + 1]);
                    l1[2 * i]     = fma2(bb, ww.x, l1[2 * i]);
                    l1[2 * i + 1] = fma2(bb, ww.y, l1[2 * i + 1]);
                }
            }
        }
#pragma unroll
        for (int i = 0; i < 8; i++) {
            int c0 = hh * 16 + 2 * i;
            if (c0 < 27) {
                float lo, hi;
                unpack2(lo, hi, l0[i]);
                oa[c0] = lo;
                if (c0 + 1 < 27) oa[c0 + 1] = hi;
                unpack2(lo, hi, l1[i]);
                ob[c0] = lo;
                if (c0 + 1 < 27) ob[c0 + 1] = hi;
            }
        }
    }
    __syncthreads();

    // ---- write out (~coalesced remap) ----
    {
        const int hbase = (int)blockIdx.x * 256;
#pragma unroll
        for (int b = 0; b < 6912; b += TPB) {   // 54 iters exactly
            int i = b + tid;
            int hl = i / 27;
            int c = i - hl * 27;
            int hrow = hbase + hl;
            int batch = hrow / 5;
            int tt = hrow - batch * 5;          // 0..4 -> t = 3+tt
            g_out[(size_t)batch * 216 + (3 + tt) * 27 + c] = s_out[i];
        }
    }
}

extern "C" void kernel_launch(void* const* d_in, const int* in_sizes, int n_in,
                              void* d_out, int out_size) {
    const int*   tokens = (const int*)d_in[0];
    const float* tokE   = (const float*)d_in[1];
    const float* posE   = (const float*)d_in[2];
    const float* Wq     = (const float*)d_in[3];
    const float* Wk     = (const float*)d_in[4];
    const float* Wv     = (const float*)d_in[5];
    const float* W1     = (const float*)d_in[6];
    const float* W2     = (const float*)d_in[7];
    const float* Wout   = (const float*)d_in[8];
    float*       out    = (float*)d_out;

    cudaFuncSetAttribute(mt_kernel, cudaFuncAttributeMaxDynamicSharedMemorySize,
                         SMEM_BYTES);

    const int rows    = in_sizes[0];          // B*T = 1048576
    const int batches = rows / 8;             // 131072
    const int heavy   = batches * 5;          // 655360
    const int na      = heavy / 256;          // 2560 (exact)
    const int nb      = batches / (4 * BPW);  // 4096 (exact)

    ek_kernel<<<216, TPB>>>(tokE, posE, Wq, Wk, Wv);
    ttab_kernel<<<(20439 * 32 + TPB - 1) / TPB, TPB>>>(tokE, posE, W1, W2, Wout);
    mt_kernel<<<na + nb, TPB, SMEM_BYTES>>>(tokens, tokE, posE, W1, W2, Wout,
                                            out, na);
}

// round 17
// speedup vs baseline: 1.2444x; 1.2444x over previous
#include <cuda_runtime.h>
#include <cstdint>

#define TPB 128

// ---------------- precomputed tables (device globals; no allocation) --------
__device__ float g_Vtab[216 * 32];
__device__ float g_Etab[216 * 216];     // exp(score)
__device__ float g_Ttab[20439 * 27];    // outputs for all prefixes with t<=2

// ---------------- packed f32x2 helpers ----------------
__device__ __forceinline__ unsigned long long fma2(unsigned long long a,
                                                   unsigned long long b,
                                                   unsigned long long c) {
    unsigned long long d;
    asm("fma.rn.f32x2 %0, %1, %2, %3;" : "=l"(d) : "l"(a), "l"(b), "l"(c));
    return d;
}
__device__ __forceinline__ unsigned long long pack2(float lo, float hi) {
    unsigned long long r;
    asm("mov.b64 %0, {%1, %2};" : "=l"(r) : "f"(lo), "f"(hi));
    return r;
}
__device__ __forceinline__ void unpack2(float& lo, float& hi, unsigned long long v) {
    asm("mov.b64 {%0, %1}, %2;" : "=f"(lo), "=f"(hi) : "l"(v));
}

// ------- merged pre-kernel: E (exp scores) + V table, block per k-row -------
// score(q,k) = x_q . (Wq . K_k)  -- no Q/K tables needed.
__global__ void ek_kernel(const float* __restrict__ tokE,
                          const float* __restrict__ posE,
                          const float* __restrict__ Wq,
                          const float* __restrict__ Wk,
                          const float* __restrict__ Wv) {
    __shared__ float xk[32], kk[32], uu[32];
    const int rk  = blockIdx.x;          // 0..215
    const int tok = rk >> 3, s = rk & 7;
    const int tid = threadIdx.x;
    if (tid < 32) xk[tid] = tokE[tok * 32 + tid] + posE[s * 32 + tid];
    __syncthreads();
    if (tid < 32) {
        float k = 0.f, v = 0.f;
#pragma unroll
        for (int d = 0; d < 32; d++) {
            k += xk[d] * Wk[d * 32 + tid];
            v += xk[d] * Wv[d * 32 + tid];
        }
        kk[tid] = k;
        g_Vtab[rk * 32 + tid] = v;
    }
    __syncthreads();
    if (tid < 32) {
        float u = 0.f;
#pragma unroll
        for (int n = 0; n < 32; n++) u += Wq[tid * 32 + n] * kk[n];
        uu[tid] = u;
    }
    __syncthreads();
    for (int rq = tid; rq < 216; rq += TPB) {
        int tq = rq & 7, tkq = rq >> 3;
        float acc = 0.f;
#pragma unroll
        for (int d = 0; d < 32; d++)
            acc += (tokE[tkq * 32 + d] + posE[tq * 32 + d]) * uu[d];
        g_Etab[rq * 216 + rk] = __expf(acc);   // scores O(1e-4): safe w/o max
    }
}

// ---------------- warp-level layernorm (lane = dim) ----------------
__device__ __forceinline__ float ln_warp(float v) {
    float s1 = v, s2 = v * v;
#pragma unroll
    for (int off = 16; off; off >>= 1) {
        s1 += __shfl_xor_sync(0xffffffffu, s1, off);
        s2 += __shfl_xor_sync(0xffffffffu, s2, off);
    }
    float mu  = s1 * (1.0f / 32.0f);
    float var = s2 * (1.0f / 32.0f) - mu * mu;
    return (v - mu) * rsqrtf(var + 1e-5f);
}

// ---------------- pre-kernel: prefix table, WARP per entry ----------------
__global__ void ttab_kernel(const float* __restrict__ tokE,
                            const float* __restrict__ posE,
                            const float* __restrict__ W1,
                            const float* __restrict__ W2,
                            const float* __restrict__ Wout) {
    const int wid  = (blockIdx.x * blockDim.x + threadIdx.x) >> 5;
    const int lane = threadIdx.x & 31;
    if (wid >= 20439) return;
    const int i = wid;
    int t, tk0 = 0, tk1 = 0, tk2 = 0;
    if (i < 27)       { t = 0; tk0 = i; }
    else if (i < 756) { t = 1; int j = i - 27; tk0 = j / 27; tk1 = j - tk0 * 27; }
    else              { t = 2; int j = i - 756; tk0 = j / 729;
                        tk1 = (j - tk0 * 729) / 27; tk2 = j - tk0 * 729 - tk1 * 27; }
    const int tokt = (t == 0) ? tk0 : ((t == 1) ? tk1 : tk2);
    const int d = lane;

    const float* E = g_Etab + (tokt * 8 + t) * 216;
    float w0 = E[tk0 * 8 + 0];
    float w1 = (t >= 1) ? E[tk1 * 8 + 1] : 0.0f;
    float w2 = (t >= 2) ? E[tk2 * 8 + 2] : 0.0f;
    const float inv = 1.0f / (w0 + w1 + w2);

    float n1 = tokE[tokt * 32 + d] + posE[t * 32 + d];
    n1 += (w0 * inv) * g_Vtab[(tk0 * 8 + 0) * 32 + d];
    if (t >= 1) n1 += (w1 * inv) * g_Vtab[(tk1 * 8 + 1) * 32 + d];
    if (t >= 2) n1 += (w2 * inv) * g_Vtab[(tk2 * 8 + 2) * 32 + d];
    n1 = ln_warp(n1);

    float h0 = 0.f, h1 = 0.f;
#pragma unroll
    for (int dd = 0; dd < 32; dd++) {
        float nd = __shfl_sync(0xffffffffu, n1, dd);
        h0 += nd * W1[dd * 64 + lane];
        h1 += nd * W1[dd * 64 + lane + 32];
    }
    h0 = fmaxf(h0, 0.f);
    h1 = fmaxf(h1, 0.f);
    float y = 0.f;
#pragma unroll
    for (int n = 0; n < 32; n++) {
        float a = __shfl_sync(0xffffffffu, h0, n);
        float b = __shfl_sync(0xffffffffu, h1, n);
        y += a * W2[n * 32 + d];
        y += b * W2[(n + 32) * 32 + d];
    }
    float n2 = ln_warp(y + n1);

    float acc = 0.f;
#pragma unroll
    for (int dd = 0; dd < 32; dd++) {
        float nd = __shfl_sync(0xffffffffu, n2, dd);
        acc += nd * ((lane < 27) ? Wout[dd * 27 + lane] : 0.0f);
    }
    if (lane < 27) g_Ttab[i * 27 + lane] = acc;
}

// ---------------- main kernel smem layout (floats) ----------------
static constexpr int OFF_W1   = 0;      // 32 x 64
static constexpr int OFF_W2   = 2048;   // 64 x 32
static constexpr int OFF_WOUT = 4096;   // 32 x 28 padded
static constexpr int OFF_TOKE = 4992;   // 27 x 36
static constexpr int OFF_POSE = 5964;   // 8 x 36
static constexpr int OFF_VT   = 6252;   // 216 x 36  (V table; reused for out)
static constexpr int SMEM_FLOATS = 14028;
static constexpr int SMEM_BYTES  = SMEM_FLOATS * 4;   // 56112 B

extern __shared__ float sm[];

__device__ __forceinline__ void layernorm32(float* v) {
    float s1 = 0.0f, s2 = 0.0f;
#pragma unroll
    for (int e = 0; e < 32; e++) { s1 += v[e]; s2 += v[e] * v[e]; }
    float mu  = s1 * (1.0f / 32.0f);
    float var = s2 * (1.0f / 32.0f) - mu * mu;
    float rs  = rsqrtf(var + 1e-5f);
#pragma unroll
    for (int e = 0; e < 32; e++) v[e] = (v[e] - mu) * rs;
}

#define BPW 8   // batches per warp in the light path

__global__ void __launch_bounds__(TPB, 3)
mt_kernel(const int* __restrict__ tokens,
          const float* __restrict__ g_tokE, const float* __restrict__ g_posE,
          const float* __restrict__ g_W1,  const float* __restrict__ g_W2,
          const float* __restrict__ g_Wout,
          float* __restrict__ g_out,
          int na_blocks)
{
    const int tid = threadIdx.x;

    // ============ LIGHT PATH: t<=2 rows, warp-per-batch table copy =========
    if ((int)blockIdx.x >= na_blocks) {
        const int lane = tid & 31;
        const int gw = ((int)blockIdx.x - na_blocks) * 4 + (tid >> 5);
        const int bbase = gw * BPW;
        int4 tt[BPW];
#pragma unroll
        for (int b = 0; b < BPW; b++)
            tt[b] = *(const int4*)(tokens + (bbase + b) * 8);
#pragma unroll
        for (int b = 0; b < BPW; b++) {
            const int batch = bbase + b;
            const int idx0 = tt[b].x;
            const int idx1 = 27 + tt[b].x * 27 + tt[b].y;
            const int idx2 = 756 + tt[b].x * 729 + tt[b].y * 27 + tt[b].z;
            float* ob = g_out + (size_t)batch * 216;
#pragma unroll
            for (int k = 0; k < 3; k++) {
                int r = lane + 32 * k;
                if (r < 81) {
                    int t = (r >= 54) ? 2 : ((r >= 27) ? 1 : 0);
                    int c = r - t * 27;
                    int idx = (t == 0) ? idx0 : ((t == 1) ? idx1 : idx2);
                    ob[r] = __ldg(g_Ttab + idx * 27 + c);
                }
            }
        }
        return;
    }

    // ================= HEAVY PATH: t in 3..7 ================================
    float* s_W1   = sm + OFF_W1;
    float* s_W2   = sm + OFF_W2;
    float* s_Wout = sm + OFF_WOUT;
    float* s_tokE = sm + OFF_TOKE;
    float* s_posE = sm + OFF_POSE;
    float* s_VT   = sm + OFF_VT;

    // row mapping: hrow = batch*5 + (t-3)
    const int hrow0 = (int)blockIdx.x * 256 + tid;
    const int hrow1 = hrow0 + TPB;
    const int batch0 = hrow0 / 5;
    const int batch1 = hrow1 / 5;
    const int t0 = hrow0 - batch0 * 5 + 3;   // 3..7
    const int t1 = hrow1 - batch1 * 5 + 3;

    // ---- EARLY: token + score gathers (hide under staging stores) ----
    const int4 ta0 = *(const int4*)(tokens + batch0 * 8);
    const int4 tb0 = *(const int4*)(tokens + batch0 * 8 + 4);
    const int4 ta1 = *(const int4*)(tokens + batch1 * 8);
    const int4 tb1 = *(const int4*)(tokens + batch1 * 8 + 4);
    const int tk0[8] = {ta0.x, ta0.y, ta0.z, ta0.w, tb0.x, tb0.y, tb0.z, tb0.w};
    const int tk1[8] = {ta1.x, ta1.y, ta1.z, ta1.w, tb1.x, tb1.y, tb1.z, tb1.w};
    const int tok0 = tk0[t0 & 7] & 31;
    const int tok1 = tk1[t1 & 7] & 31;

    const int sb0 = (tok0 * 8 + t0) * 216;
    const int sb1 = (tok1 * 8 + t1) * 216;
    float p0[8], p1[8];
#pragma unroll
    for (int s = 0; s < 8; s++) {
        p0[s] = __ldg(g_Etab + sb0 + tk0[s] * 8 + s);
        p1[s] = __ldg(g_Etab + sb1 + tk1[s] * 8 + s);
    }

    // ---- cooperative staging ----
#pragma unroll
    for (int b = 0; b < 2048; b += TPB * 4) {
        int i = b + tid * 4;
        *(float4*)(s_W1 + i) = *(const float4*)(g_W1 + i);
        *(float4*)(s_W2 + i) = *(const float4*)(g_W2 + i);
    }
    for (int i = tid; i < 32 * 28; i += TPB) {
        int e = i / 28, c = i % 28;
        s_Wout[i] = (c < 27) ? g_Wout[e * 27 + c] : 0.0f;
    }
    for (int i = tid; i < 27 * 32; i += TPB) {
        int r = i >> 5, c = i & 31;
        s_tokE[r * 36 + c] = g_tokE[i];
    }
    for (int i = tid; i < 8 * 32; i += TPB) {
        int r = i >> 5, c = i & 31;
        s_posE[r * 36 + c] = g_posE[i];
    }
    for (int i = tid; i < 216 * 8; i += TPB) {
        int r = i >> 3, c = i & 7;
        *(float4*)(s_VT + r * 36 + c * 4) = *(const float4*)(g_Vtab + r * 32 + c * 4);
    }
    __syncthreads();

    // ---- softmax weights (causal; exp already applied) ----
    float sum0 = 0.0f, sum1 = 0.0f;
#pragma unroll
    for (int s = 0; s < 8; s++) {
        p0[s] = (s <= t0) ? p0[s] : 0.0f;
        p1[s] = (s <= t1) ? p1[s] : 0.0f;
        sum0 += p0[s]; sum1 += p1[s];
    }
    const float inv0 = 1.0f / sum0;
    const float inv1 = 1.0f / sum1;

    // ---- out = attn @ V ----
    unsigned long long o0[16], o1[16];
#pragma unroll
    for (int i = 0; i < 16; i++) { o0[i] = 0ULL; o1[i] = 0ULL; }
#pragma unroll
    for (int s = 0; s < 8; s++) {
        float a = p0[s] * inv0;
        float b = p1[s] * inv1;
        unsigned long long aa = pack2(a, a);
        unsigned long long bb = pack2(b, b);
        const ulonglong2* va = (const ulonglong2*)(s_VT + (tk0[s] * 8 + s) * 36);
        const ulonglong2* vb = (const ulonglong2*)(s_VT + (tk1[s] * 8 + s) * 36);
#pragma unroll
        for (int i = 0; i < 8; i++) {
            ulonglong2 wa = va[i], wb = vb[i];
            o0[2 * i]     = fma2(aa, wa.x, o0[2 * i]);
            o0[2 * i + 1] = fma2(aa, wa.y, o0[2 * i + 1]);
            o1[2 * i]     = fma2(bb, wb.x, o1[2 * i]);
            o1[2 * i + 1] = fma2(bb, wb.y, o1[2 * i + 1]);
        }
    }

    // ---- LN1(out + x) ----
    float n1a[32], n1b[32];
#pragma unroll
    for (int i = 0; i < 8; i++) {
        float4 pa = *(const float4*)(s_posE + t0 * 36 + i * 4);
        float4 pb = *(const float4*)(s_posE + t1 * 36 + i * 4);
        float4 xa = *(const float4*)(s_tokE + tok0 * 36 + i * 4);
        float4 xb = *(const float4*)(s_tokE + tok1 * 36 + i * 4);
        float lo, hi;
        unpack2(lo, hi, o0[2 * i]);
        n1a[4 * i + 0] = lo + xa.x + pa.x;
        n1a[4 * i + 1] = hi + xa.y + pa.y;
        unpack2(lo, hi, o0[2 * i + 1]);
        n1a[4 * i + 2] = lo + xa.z + pa.z;
        n1a[4 * i + 3] = hi + xa.w + pa.w;
        unpack2(lo, hi, o1[2 * i]);
        n1b[4 * i + 0] = lo + xb.x + pb.x;
        n1b[4 * i + 1] = hi + xb.y + pb.y;
        unpack2(lo, hi, o1[2 * i + 1]);
        n1b[4 * i + 2] = lo + xb.z + pb.z;
        n1b[4 * i + 3] = hi + xb.w + pb.w;
    }
    layernorm32(n1a);
    layernorm32(n1b);

    // ---- MLP: relu(n1 @ W1) @ W2, h in 8 chunks of 8 ----
    unsigned long long y0[16], y1[16];
#pragma unroll
    for (int i = 0; i < 16; i++) { y0[i] = 0ULL; y1[i] = 0ULL; }
#pragma unroll 1
    for (int c = 0; c < 8; c++) {
        unsigned long long h0[4], h1[4];
#pragma unroll
        for (int i = 0; i < 4; i++) { h0[i] = 0ULL; h1[i] = 0ULL; }
#pragma unroll
        for (int e = 0; e < 32; e++) {
            unsigned long long b0v = pack2(n1a[e], n1a[e]);
            unsigned long long b1v = pack2(n1b[e], n1b[e]);
            const ulonglong2* w = (const ulonglong2*)(s_W1 + e * 64 + c * 8);
#pragma unroll
            for (int i = 0; i < 2; i++) {
                ulonglong2 ww = w[i];
                h0[2 * i]     = fma2(b0v, ww.x, h0[2 * i]);
                h0[2 * i + 1] = fma2(b0v, ww.y, h0[2 * i + 1]);
                h1[2 * i]     = fma2(b1v, ww.x, h1[2 * i]);
                h1[2 * i + 1] = fma2(b1v, ww.y, h1[2 * i + 1]);
            }
        }
#pragma unroll
        for (int j = 0; j < 4; j++) {
            float ha0, ha1, hb0, hb1;
            unpack2(ha0, ha1, h0[j]);
            unpack2(hb0, hb1, h1[j]);
            ha0 = fmaxf(ha0, 0.0f); ha1 = fmaxf(ha1, 0.0f);
            hb0 = fmaxf(hb0, 0.0f); hb1 = fmaxf(hb1, 0.0f);
            const ulonglong2* wa =
                (const ulonglong2*)(s_W2 + (c * 8 + 2 * j) * 32);
            {
                unsigned long long pa = pack2(ha0, ha0);
                unsigned long long pb = pack2(hb0, hb0);
#pragma unroll
                for (int i = 0; i < 8; i++) {
                    ulonglong2 ww = wa[i];
                    y0[2 * i]     = fma2(pa, ww.x, y0[2 * i]);
                    y0[2 * i + 1] = fma2(pa, ww.y, y0[2 * i + 1]);
                    y1[2 * i]     = fma2(pb, ww.x, y1[2 * i]);
                    y1[2 * i + 1] = fma2(pb, ww.y, y1[2 * i + 1]);
                }
            }
            {
                unsigned long long pa = pack2(ha1, ha1);
                unsigned long long pb = pack2(hb1, hb1);
                const ulonglong2* wb = wa + 8;
#pragma unroll
                for (int i = 0; i < 8; i++) {
                    ulonglong2 ww = wb[i];
                    y0[2 * i]     = fma2(pa, ww.x, y0[2 * i]);
                    y0[2 * i + 1] = fma2(pa, ww.y, y0[2 * i + 1]);
                    y1[2 * i]     = fma2(pb, ww.x, y1[2 * i]);
                    y1[2 * i + 1] = fma2(pb, ww.y, y1[2 * i + 1]);
                }
            }
        }
    }

    // ---- LN2(y + n1) ----
    float n2a[32], n2b[32];
#pragma unroll
    for (int i = 0; i < 16; i++) {
        float lo, hi;
        unpack2(lo, hi, y0[i]);
        n2a[2 * i] = lo + n1a[2 * i];  n2a[2 * i + 1] = hi + n1a[2 * i + 1];
        unpack2(lo, hi, y1[i]);
        n2b[2 * i] = lo + n1b[2 * i];  n2b[2 * i + 1] = hi + n1b[2 * i + 1];
    }
    layernorm32(n2a);
    layernorm32(n2b);

    // ---- logits = n2 @ Wout (28-padded) ----
    unsigned long long l0[14], l1[14];
#pragma unroll
    for (int i = 0; i < 14; i++) { l0[i] = 0ULL; l1[i] = 0ULL; }
#pragma unroll
    for (int e = 0; e < 32; e++) {
        unsigned long long b0v = pack2(n2a[e], n2a[e]);
        unsigned long long b1v = pack2(n2b[e], n2b[e]);
        const ulonglong2* w = (const ulonglong2*)(s_Wout + e * 28);
#pragma unroll
        for (int i = 0; i < 7; i++) {
            ulonglong2 ww = w[i];
            l0[2 * i]     = fma2(b0v, ww.x, l0[2 * i]);
            l0[2 * i + 1] = fma2(b0v, ww.y, l0[2 * i + 1]);
            l1[2 * i]     = fma2(b1v, ww.x, l1[2 * i]);
            l1[2 * i + 1] = fma2(b1v, ww.y, l1[2 * i + 1]);
        }
    }

    // ---- stage outputs (reuse V-table region), write ~coalesced ----
    __syncthreads();
    float* s_out = s_VT;   // 256*27 = 6912 floats <= 7776
    {
        float* oa = s_out + tid * 27;
        float* ob = s_out + (TPB + tid) * 27;
#pragma unroll
        for (int i = 0; i < 13; i++) {
            float lo, hi;
            unpack2(lo, hi, l0[i]); oa[2 * i] = lo; oa[2 * i + 1] = hi;
            unpack2(lo, hi, l1[i]); ob[2 * i] = lo; ob[2 * i + 1] = hi;
        }
        float lo, hi;
        unpack2(lo, hi, l0[13]); oa[26] = lo;
        unpack2(lo, hi, l1[13]); ob[26] = lo;
    }
    __syncthreads();
    {
        const int hbase = (int)blockIdx.x * 256;
#pragma unroll
        for (int b = 0; b < 6912; b += TPB) {   // 54 iters exactly
            int i = b + tid;
            int hl = i / 27;
            int c = i - hl * 27;
            int hrow = hbase + hl;
            int batch = hrow / 5;
            int tt = hrow - batch * 5;          // 0..4 -> t = 3+tt
            g_out[(size_t)batch * 216 + (3 + tt) * 27 + c] = s_out[i];
        }
    }
}

extern "C" void kernel_launch(void* const* d_in, const int* in_sizes, int n_in,
                              void* d_out, int out_size) {
    const int*   tokens = (const int*)d_in[0];
    const float* tokE   = (const float*)d_in[1];
    const float* posE   = (const float*)d_in[2];
    const float* Wq     = (const float*)d_in[3];
    const float* Wk     = (const float*)d_in[4];
    const float* Wv     = (const float*)d_in[5];
    const float* W1     = (const float*)d_in[6];
    const float* W2     = (const float*)d_in[7];
    const float* Wout   = (const float*)d_in[8];
    float*       out    = (float*)d_out;

    cudaFuncSetAttribute(mt_kernel, cudaFuncAttributeMaxDynamicSharedMemorySize,
                         SMEM_BYTES);

    const int rows    = in_sizes[0];          // B*T = 1048576
    const int batches = rows / 8;             // 131072
    const int heavy   = batches * 5;          // 655360
    const int na      = heavy / 256;          // 2560 (exact)
    const int nb      = batches / (4 * BPW);  // 4096 (exact)

    ek_kernel<<<216, TPB>>>(tokE, posE, Wq, Wk, Wv);
    ttab_kernel<<<(20439 * 32 + TPB - 1) / TPB, TPB>>>(tokE, posE, W1, W2, Wout);
    mt_kernel<<<na + nb, TPB, SMEM_BYTES>>>(tokens, tokE, posE, W1, W2, Wout,
                                            out, na);
}